// round 2
// baseline (speedup 1.0000x reference)
#include <cuda_runtime.h>

// Problem constants (fixed by the reference).
namespace {
constexpr int Bt  = 4096;   // batch
constexpr int En  = 128;    // edges
constexpr int IPc = 64;     // input dim
constexpr int Hc  = 100;    // hidden dim
constexpr int TB  = 256;    // rows (b) per CTA
constexpr float EPSc   = 1e-5f;
constexpr float SLOPEc = 0.01f;

// SMEM layout (floats): W1 | W2 | h1[Hc][TB] | b1 g1 be1 b2 g2 be2 Wo gw | C1 C2
constexpr int SM_W1  = 0;
constexpr int SM_W2  = SM_W1 + IPc * Hc;          // 6400
constexpr int SM_H   = SM_W2 + Hc * Hc;           // 16400
constexpr int SM_B1  = SM_H  + Hc * TB;           // 42000
constexpr int SM_G1  = SM_B1 + Hc;
constexpr int SM_BE1 = SM_G1 + Hc;
constexpr int SM_B2  = SM_BE1 + Hc;
constexpr int SM_G2  = SM_B2 + Hc;
constexpr int SM_BE2 = SM_G2 + Hc;
constexpr int SM_WO  = SM_BE2 + Hc;
constexpr int SM_GW  = SM_WO + Hc;
constexpr int SM_C   = SM_GW + Hc;                // [0]=C1, [1]=C2
constexpr int SMEM_FLOATS = SM_C + 2;             // 42802 floats = 171208 B
}

__global__ __launch_bounds__(TB, 1)
void fused_edge_mlp(const float* __restrict__ x,
                    const float* __restrict__ W1, const float* __restrict__ b1,
                    const float* __restrict__ g1, const float* __restrict__ be1,
                    const float* __restrict__ W2, const float* __restrict__ b2,
                    const float* __restrict__ g2, const float* __restrict__ be2,
                    const float* __restrict__ Wo, const float* __restrict__ bo,
                    float* __restrict__ out)
{
    extern __shared__ float sm[];
    float* W1s  = sm + SM_W1;
    float* W2s  = sm + SM_W2;
    float* hs   = sm + SM_H;
    float* b1s  = sm + SM_B1;
    float* g1s  = sm + SM_G1;
    float* be1s = sm + SM_BE1;
    float* b2s  = sm + SM_B2;
    float* be2s = sm + SM_BE2;
    float* Wos  = sm + SM_WO;
    float* gws  = sm + SM_GW;
    float* Cs   = sm + SM_C;

    const int tid = threadIdx.x;
    const int e   = blockIdx.y;
    const int b   = blockIdx.x * TB + tid;

    // ---- stage weights for this edge ----
    {
        const float* p = W1 + (size_t)e * (IPc * Hc);
        for (int i = tid; i < IPc * Hc; i += TB) W1s[i] = p[i];
        const float* q = W2 + (size_t)e * (Hc * Hc);
        for (int i = tid; i < Hc * Hc; i += TB) W2s[i] = q[i];
        if (tid < Hc) {
            b1s[tid]  = b1 [e * Hc + tid];
            g1s[tid]  = g1 [e * Hc + tid];
            be1s[tid] = be1[e * Hc + tid];
            b2s[tid]  = b2 [e * Hc + tid];
            float gg  = g2 [e * Hc + tid];
            float bb  = be2[e * Hc + tid];
            be2s[tid] = bb;
            float wo  = Wo [e * Hc + tid];
            Wos[tid]  = wo;
            gws[tid]  = gg * wo;
        }
        if (tid == 0) {
            // per-edge epilogue constants: C1 = sum g2*Wo, C2 = sum be2*Wo
            // (cheap serial loop once per CTA; overlapped with other threads'
            //  W2 staging only after their vector writes -> do after syncthreads
            //  would race; instead compute from global directly)
            float c1 = 0.f, c2 = 0.f;
            const float* g2p  = g2  + e * Hc;
            const float* be2p = be2 + e * Hc;
            const float* wop  = Wo  + e * Hc;
            #pragma unroll 4
            for (int j = 0; j < Hc; j++) {
                const float wo = wop[j];
                c1 = fmaf(g2p[j],  wo, c1);
                c2 = fmaf(be2p[j], wo, c2);
            }
            Cs[0] = c1;
            Cs[1] = c2 + bo[e];
        }
    }
    __syncthreads();

    // ---- x row into registers (16 x float4, 256B contiguous per thread) ----
    float xr[IPc];
    {
        const float4* xp = reinterpret_cast<const float4*>(
            x + ((size_t)b * En + e) * IPc);
        #pragma unroll
        for (int i = 0; i < IPc / 4; i++) {
            float4 v = xp[i];
            xr[4*i+0] = v.x; xr[4*i+1] = v.y; xr[4*i+2] = v.z; xr[4*i+3] = v.w;
        }
    }

    const float inv = 1.0f / (float)Hc;

    // ---- layer 1: h = leaky(x@W1 + b1), accumulate LN stats, stash h ----
    float sum = 0.f, sq = 0.f;
    #pragma unroll 1
    for (int jg = 0; jg < Hc / 4; jg++) {
        const int j = jg * 4;
        float a0 = b1s[j+0], a1 = b1s[j+1], a2 = b1s[j+2], a3 = b1s[j+3];
        #pragma unroll
        for (int k = 0; k < IPc; k++) {
            const float4 w = *reinterpret_cast<const float4*>(W1s + k * Hc + j);
            a0 = fmaf(xr[k], w.x, a0);
            a1 = fmaf(xr[k], w.y, a1);
            a2 = fmaf(xr[k], w.z, a2);
            a3 = fmaf(xr[k], w.w, a3);
        }
        a0 = a0 > 0.f ? a0 : SLOPEc * a0;
        a1 = a1 > 0.f ? a1 : SLOPEc * a1;
        a2 = a2 > 0.f ? a2 : SLOPEc * a2;
        a3 = a3 > 0.f ? a3 : SLOPEc * a3;
        sum += (a0 + a1) + (a2 + a3);
        sq   = fmaf(a0, a0, sq); sq = fmaf(a1, a1, sq);
        sq   = fmaf(a2, a2, sq); sq = fmaf(a3, a3, sq);
        hs[(j+0) * TB + tid] = a0;
        hs[(j+1) * TB + tid] = a1;
        hs[(j+2) * TB + tid] = a2;
        hs[(j+3) * TB + tid] = a3;
    }
    {
        const float mean = sum * inv;
        const float rs   = rsqrtf(fmaf(-mean, mean, sq * inv) + EPSc);
        #pragma unroll 1
        for (int j = 0; j < Hc; j++) {
            const float v = hs[j * TB + tid];
            hs[j * TB + tid] = fmaf((v - mean) * rs, g1s[j], be1s[j]);
        }
    }

    // ---- layer 2 + head, with LN2 folded algebraically (no h2 storage) ----
    float sum2 = 0.f, sq2 = 0.f, dvw = 0.f;
    #pragma unroll 1
    for (int jg = 0; jg < Hc / 4; jg++) {
        const int j = jg * 4;
        float a0 = b2s[j+0], a1 = b2s[j+1], a2 = b2s[j+2], a3 = b2s[j+3];
        #pragma unroll 4
        for (int k = 0; k < Hc; k++) {
            const float  hv = hs[k * TB + tid];
            const float4 w  = *reinterpret_cast<const float4*>(W2s + k * Hc + j);
            a0 = fmaf(hv, w.x, a0);
            a1 = fmaf(hv, w.y, a1);
            a2 = fmaf(hv, w.z, a2);
            a3 = fmaf(hv, w.w, a3);
        }
        a0 = a0 > 0.f ? a0 : SLOPEc * a0;
        a1 = a1 > 0.f ? a1 : SLOPEc * a1;
        a2 = a2 > 0.f ? a2 : SLOPEc * a2;
        a3 = a3 > 0.f ? a3 : SLOPEc * a3;
        sum2 += (a0 + a1) + (a2 + a3);
        sq2   = fmaf(a0, a0, sq2); sq2 = fmaf(a1, a1, sq2);
        sq2   = fmaf(a2, a2, sq2); sq2 = fmaf(a3, a3, sq2);
        dvw   = fmaf(a0, gws[j+0], dvw);
        dvw   = fmaf(a1, gws[j+1], dvw);
        dvw   = fmaf(a2, gws[j+2], dvw);
        dvw   = fmaf(a3, gws[j+3], dvw);
    }
    {
        const float mean2 = sum2 * inv;
        const float rs2   = rsqrtf(fmaf(-mean2, mean2, sq2 * inv) + EPSc);
        // out = rs*(dvw - m*C1) + C2(+bo),  C1 = sum g2*Wo, C2 = sum be2*Wo
        const float o = fmaf(rs2, fmaf(-mean2, Cs[0], dvw), Cs[1]);
        out[(size_t)e * Bt + b] = o;
    }
}

extern "C" void kernel_launch(void* const* d_in, const int* in_sizes, int n_in,
                              void* d_out, int out_size)
{
    const float* x   = (const float*)d_in[0];
    const float* W1  = (const float*)d_in[1];
    const float* b1  = (const float*)d_in[2];
    const float* g1  = (const float*)d_in[3];
    const float* be1 = (const float*)d_in[4];
    const float* W2  = (const float*)d_in[5];
    const float* b2  = (const float*)d_in[6];
    const float* g2  = (const float*)d_in[7];
    const float* be2 = (const float*)d_in[8];
    const float* Wo  = (const float*)d_in[9];
    const float* bo  = (const float*)d_in[10];
    float* out = (float*)d_out;

    const size_t smem = (size_t)SMEM_FLOATS * sizeof(float);   // 171208 B
    cudaFuncSetAttribute(fused_edge_mlp,
                         cudaFuncAttributeMaxDynamicSharedMemorySize, (int)smem);

    dim3 grid(Bt / TB, En);   // (16, 128)
    fused_edge_mlp<<<grid, TB, smem>>>(x, W1, b1, g1, be1,
                                       W2, b2, g2, be2, Wo, bo, out);
}

// round 5
// speedup vs baseline: 1.6282x; 1.6282x over previous
#include <cuda_runtime.h>
#include <cuda_fp16.h>

namespace {
constexpr int Bt  = 4096;
constexpr int En  = 128;
constexpr int IPc = 64;
constexpr int Hc  = 100;
constexpr int TB  = 256;         // threads per CTA
constexpr int RPC = TB * 2;      // 512 rows per CTA (2 rows/thread)
constexpr float EPSc   = 1e-5f;
constexpr float SLOPEc = 0.01f;

// smem words (4B): W1 | W2'(g1-folded) | hs(half2) | b1 | bias2' | gws | C
constexpr int SM_W1 = 0;                       // 64*100
constexpr int SM_W2 = SM_W1 + IPc * Hc;        // +100*100
constexpr int SM_H  = SM_W2 + Hc * Hc;         // +100*256 (half2 per word)
constexpr int SM_B1 = SM_H  + Hc * TB;
constexpr int SM_B2 = SM_B1 + Hc;              // bias2' = b2 + be1·W2
constexpr int SM_GW = SM_B2 + Hc;              // g2*Wo
constexpr int SM_C  = SM_GW + Hc;              // [0]=C1, [1]=C2+bo
constexpr int SMEM_WORDS = SM_C + 2;           // 42302 words = 169208 B
}

__global__ __launch_bounds__(TB, 1)
void fused_edge_mlp_r2(const float* __restrict__ x,
                       const float* __restrict__ W1, const float* __restrict__ b1,
                       const float* __restrict__ g1, const float* __restrict__ be1,
                       const float* __restrict__ W2, const float* __restrict__ b2,
                       const float* __restrict__ g2, const float* __restrict__ be2,
                       const float* __restrict__ Wo, const float* __restrict__ bo,
                       float* __restrict__ out)
{
    extern __shared__ float sm[];
    float*    W1s = sm + SM_W1;
    float*    W2s = sm + SM_W2;
    __half2*  hs  = reinterpret_cast<__half2*>(sm + SM_H);
    float*    b1s = sm + SM_B1;
    float*    b2s = sm + SM_B2;
    float*    gws = sm + SM_GW;
    float*    Cs  = sm + SM_C;

    const int tid = threadIdx.x;
    const int e   = blockIdx.y;

    // ---- stage weights (W2 pre-multiplied by g1; biases folded) ----
    {
        const float* p = W1 + (size_t)e * (IPc * Hc);
        for (int i = tid; i < IPc * Hc; i += TB) W1s[i] = p[i];
        const float* q = W2 + (size_t)e * (Hc * Hc);
        for (int i = tid; i < Hc * Hc; i += TB) {
            const int k = i / Hc;
            W2s[i] = q[i] * __ldg(g1 + e * Hc + k);
        }
        if (tid < Hc) {
            b1s[tid] = b1[e * Hc + tid];
            gws[tid] = g2[e * Hc + tid] * Wo[e * Hc + tid];
            // bias2'[j] = b2[j] + sum_k be1[k]*W2[k][j]
            float acc = b2[e * Hc + tid];
            const float* be1p = be1 + e * Hc;
            #pragma unroll 4
            for (int k = 0; k < Hc; k++)
                acc = fmaf(__ldg(be1p + k), __ldg(q + k * Hc + tid), acc);
            b2s[tid] = acc;
        }
        if (tid == 0) {
            float c1 = 0.f, c2 = 0.f;
            const float* g2p  = g2  + e * Hc;
            const float* be2p = be2 + e * Hc;
            const float* wop  = Wo  + e * Hc;
            #pragma unroll 4
            for (int j = 0; j < Hc; j++) {
                const float wo = wop[j];
                c1 = fmaf(g2p[j],  wo, c1);
                c2 = fmaf(be2p[j], wo, c2);
            }
            Cs[0] = c1;
            Cs[1] = c2 + bo[e];
        }
    }
    __syncthreads();

    const int b0  = blockIdx.x * RPC + tid;
    const int b1r = b0 + TB;
    const float inv = 1.0f / (float)Hc;

    // ---- two x rows into registers (128 fp32 regs) ----
    float xr0[IPc], xr1[IPc];
    {
        const float4* xp0 = reinterpret_cast<const float4*>(
            x + ((size_t)b0  * En + e) * IPc);
        const float4* xp1 = reinterpret_cast<const float4*>(
            x + ((size_t)b1r * En + e) * IPc);
        #pragma unroll
        for (int i = 0; i < IPc / 4; i++) {
            float4 v0 = xp0[i];
            xr0[4*i+0]=v0.x; xr0[4*i+1]=v0.y; xr0[4*i+2]=v0.z; xr0[4*i+3]=v0.w;
            float4 v1 = xp1[i];
            xr1[4*i+0]=v1.x; xr1[4*i+1]=v1.y; xr1[4*i+2]=v1.z; xr1[4*i+3]=v1.w;
        }
    }

    // ---- layer 1: 1 broadcast LDS.128 per 8 FMAs; h -> hs packed half2 ----
    float s0 = 0.f, q0 = 0.f, s1 = 0.f, q1 = 0.f;
    #pragma unroll 1
    for (int jg = 0; jg < Hc / 4; jg++) {
        const int j = jg * 4;
        const float4 bb = *reinterpret_cast<const float4*>(b1s + j);
        float a00=bb.x, a01=bb.y, a02=bb.z, a03=bb.w;
        float a10=bb.x, a11=bb.y, a12=bb.z, a13=bb.w;
        #pragma unroll
        for (int k = 0; k < IPc; k++) {
            const float4 w = *reinterpret_cast<const float4*>(W1s + k * Hc + j);
            const float x0 = xr0[k], x1 = xr1[k];
            a00 = fmaf(x0, w.x, a00); a10 = fmaf(x1, w.x, a10);
            a01 = fmaf(x0, w.y, a01); a11 = fmaf(x1, w.y, a11);
            a02 = fmaf(x0, w.z, a02); a12 = fmaf(x1, w.z, a12);
            a03 = fmaf(x0, w.w, a03); a13 = fmaf(x1, w.w, a13);
        }
        a00 = fmaxf(a00, SLOPEc*a00); a01 = fmaxf(a01, SLOPEc*a01);
        a02 = fmaxf(a02, SLOPEc*a02); a03 = fmaxf(a03, SLOPEc*a03);
        a10 = fmaxf(a10, SLOPEc*a10); a11 = fmaxf(a11, SLOPEc*a11);
        a12 = fmaxf(a12, SLOPEc*a12); a13 = fmaxf(a13, SLOPEc*a13);
        s0 += (a00+a01)+(a02+a03);
        q0 = fmaf(a00,a00,q0); q0 = fmaf(a01,a01,q0);
        q0 = fmaf(a02,a02,q0); q0 = fmaf(a03,a03,q0);
        s1 += (a10+a11)+(a12+a13);
        q1 = fmaf(a10,a10,q1); q1 = fmaf(a11,a11,q1);
        q1 = fmaf(a12,a12,q1); q1 = fmaf(a13,a13,q1);
        hs[(j+0)*TB + tid] = __floats2half2_rn(a00, a10);
        hs[(j+1)*TB + tid] = __floats2half2_rn(a01, a11);
        hs[(j+2)*TB + tid] = __floats2half2_rn(a02, a12);
        hs[(j+3)*TB + tid] = __floats2half2_rn(a03, a13);
    }

    // ---- LN1 folded into h-register reload (xr regs dead now) ----
    const float m0 = s0 * inv;
    const float r0 = rsqrtf(fmaf(-m0, m0, q0 * inv) + EPSc);
    const float m1 = s1 * inv;
    const float r1 = rsqrtf(fmaf(-m1, m1, q1 * inv) + EPSc);
    __half2 hreg[Hc];
    #pragma unroll
    for (int j = 0; j < Hc; j++) {
        const float2 f = __half22float2(hs[j*TB + tid]);
        hreg[j] = __floats2half2_rn((f.x - m0) * r0, (f.y - m1) * r1);
    }

    // ---- layer 2 + head: W2' broadcast LDS.128 per 8 FMAs, h in regs ----
    float s20=0.f, q20=0.f, s21=0.f, q21=0.f, dv0=0.f, dv1=0.f;
    #pragma unroll 1
    for (int jg = 0; jg < Hc / 4; jg++) {
        const int j = jg * 4;
        const float4 bb = *reinterpret_cast<const float4*>(b2s + j);
        float a00=bb.x, a01=bb.y, a02=bb.z, a03=bb.w;
        float a10=bb.x, a11=bb.y, a12=bb.z, a13=bb.w;
        #pragma unroll
        for (int k = 0; k < Hc; k++) {
            const float4 w = *reinterpret_cast<const float4*>(W2s + k * Hc + j);
            const float2 h = __half22float2(hreg[k]);
            a00 = fmaf(h.x, w.x, a00); a10 = fmaf(h.y, w.x, a10);
            a01 = fmaf(h.x, w.y, a01); a11 = fmaf(h.y, w.y, a11);
            a02 = fmaf(h.x, w.z, a02); a12 = fmaf(h.y, w.z, a12);
            a03 = fmaf(h.x, w.w, a03); a13 = fmaf(h.y, w.w, a13);
        }
        a00 = fmaxf(a00, SLOPEc*a00); a01 = fmaxf(a01, SLOPEc*a01);
        a02 = fmaxf(a02, SLOPEc*a02); a03 = fmaxf(a03, SLOPEc*a03);
        a10 = fmaxf(a10, SLOPEc*a10); a11 = fmaxf(a11, SLOPEc*a11);
        a12 = fmaxf(a12, SLOPEc*a12); a13 = fmaxf(a13, SLOPEc*a13);
        s20 += (a00+a01)+(a02+a03);
        q20 = fmaf(a00,a00,q20); q20 = fmaf(a01,a01,q20);
        q20 = fmaf(a02,a02,q20); q20 = fmaf(a03,a03,q20);
        s21 += (a10+a11)+(a12+a13);
        q21 = fmaf(a10,a10,q21); q21 = fmaf(a11,a11,q21);
        q21 = fmaf(a12,a12,q21); q21 = fmaf(a13,a13,q21);
        const float4 gw = *reinterpret_cast<const float4*>(gws + j);
        dv0 = fmaf(a00,gw.x,dv0); dv0 = fmaf(a01,gw.y,dv0);
        dv0 = fmaf(a02,gw.z,dv0); dv0 = fmaf(a03,gw.w,dv0);
        dv1 = fmaf(a10,gw.x,dv1); dv1 = fmaf(a11,gw.y,dv1);
        dv1 = fmaf(a12,gw.z,dv1); dv1 = fmaf(a13,gw.w,dv1);
    }
    {
        const float C1 = Cs[0], C2 = Cs[1];
        const float mm0 = s20 * inv;
        const float rr0 = rsqrtf(fmaf(-mm0, mm0, q20 * inv) + EPSc);
        out[(size_t)e * Bt + b0]  = fmaf(rr0, fmaf(-mm0, C1, dv0), C2);
        const float mm1 = s21 * inv;
        const float rr1 = rsqrtf(fmaf(-mm1, mm1, q21 * inv) + EPSc);
        out[(size_t)e * Bt + b1r] = fmaf(rr1, fmaf(-mm1, C1, dv1), C2);
    }
}

extern "C" void kernel_launch(void* const* d_in, const int* in_sizes, int n_in,
                              void* d_out, int out_size)
{
    const float* x   = (const float*)d_in[0];
    const float* W1  = (const float*)d_in[1];
    const float* b1  = (const float*)d_in[2];
    const float* g1  = (const float*)d_in[3];
    const float* be1 = (const float*)d_in[4];
    const float* W2  = (const float*)d_in[5];
    const float* b2  = (const float*)d_in[6];
    const float* g2  = (const float*)d_in[7];
    const float* be2 = (const float*)d_in[8];
    const float* Wo  = (const float*)d_in[9];
    const float* bo  = (const float*)d_in[10];
    float* out = (float*)d_out;

    const size_t smem = (size_t)SMEM_WORDS * sizeof(float);   // 169208 B
    cudaFuncSetAttribute(fused_edge_mlp_r2,
                         cudaFuncAttributeMaxDynamicSharedMemorySize, (int)smem);

    dim3 grid(Bt / RPC, En);   // (8, 128)
    fused_edge_mlp_r2<<<grid, TB, smem>>>(x, W1, b1, g1, be1,
                                          W2, b2, g2, be2, Wo, bo, out);
}